// round 1
// baseline (speedup 1.0000x reference)
#include <cuda_runtime.h>

#define NI 2000     // inner tree nodes
#define NL 10000    // leaves / vocab
#define ND 128      // docs
#define NCHUNK 48   // 8 proj chunks + 40 mass chunks, 250 dims each
#define RCHUNKS 8   // row chunks for argmax (250 rows each)

// ---- scratch (static __device__, no allocation) ----
__device__ float g_pmax[RCHUNKS * 10240];
__device__ int   g_pidx[RCHUNKS * 10240];
__device__ int   g_arg[NL];
__device__ float g_proj[ND * NI];
__device__ float g_partial[NCHUNK * ND * ND];

// ---------------------------------------------------------------------------
// Kernel 1: partial column-argmax of param (2000 x 10000), 250-row chunks.
// Coalesced: adjacent threads read adjacent columns of the same row.
// ---------------------------------------------------------------------------
__global__ __launch_bounds__(256) void argmax_partial(const float* __restrict__ param) {
    int col   = blockIdx.x * 256 + threadIdx.x;
    int chunk = blockIdx.y;
    if (col >= NL) return;
    int r0 = chunk * 250;
    const float* p = param + (size_t)r0 * NL + col;
    float m = -1e30f;
    int   mi = r0;
#pragma unroll 10
    for (int r = 0; r < 250; r++) {
        float v = p[(size_t)r * NL];
        if (v > m) { m = v; mi = r0 + r; }
    }
    g_pmax[chunk * 10240 + col] = m;
    g_pidx[chunk * 10240 + col] = mi;
}

__global__ __launch_bounds__(256) void argmax_reduce() {
    int col = blockIdx.x * 256 + threadIdx.x;
    if (col >= NL) return;
    float m  = g_pmax[col];
    int   mi = g_pidx[col];
#pragma unroll
    for (int c = 1; c < RCHUNKS; c++) {
        float v = g_pmax[c * 10240 + col];
        if (v > m) { m = v; mi = g_pidx[c * 10240 + col]; }
    }
    g_arg[col] = mi;
}

// ---------------------------------------------------------------------------
// Kernel 2: per-doc node-mass scatter + bottom-up subtree sums -> proj.
// Tree: children(r) = 5r+1 .. min(5r+5, 1999); parents are nodes 0..399.
// Levels: {156..399}, {31..155}, {6..30}, {1..5}, {0} processed bottom-up.
// ---------------------------------------------------------------------------
__global__ __launch_bounds__(256) void proj_kernel(const float* __restrict__ mass) {
    __shared__ float s[NI];
    int d   = blockIdx.x;
    int tid = threadIdx.x;
    for (int i = tid; i < NI; i += 256) s[i] = 0.f;
    __syncthreads();

    const float* mrow = mass + (size_t)d * NL;
    for (int l = tid; l < NL; l += 256)
        atomicAdd(&s[g_arg[l]], mrow[l]);
    __syncthreads();

    const int lo[5] = {156, 31, 6, 1, 0};
    const int hi[5] = {399, 155, 30, 5, 0};
#pragma unroll
    for (int ph = 0; ph < 5; ph++) {
        for (int r = lo[ph] + tid; r <= hi[ph]; r += 256) {
            int c0 = 5 * r + 1;
            float acc = s[r] + s[c0] + s[c0 + 1] + s[c0 + 2] + s[c0 + 3];
            if (c0 + 4 < NI) acc += s[c0 + 4];   // node 399 has 4 children
            s[r] = acc;
        }
        __syncthreads();
    }
    for (int i = tid; i < NI; i += 256)
        g_proj[(size_t)d * NI + i] = s[i];
}

// ---------------------------------------------------------------------------
// Kernel 3: pairwise L1 over feat = [proj(128x2000) | mass(128x10000)].
// 64x64 output tiles (upper triangle: 3 tiles), 48 dim-chunks of 250.
// 16x16 threads, 4x4 register blocking -> 2 FADD/elem, 0.5 LDS/elem.
// ---------------------------------------------------------------------------
#define KC 50
__global__ __launch_bounds__(256) void dist_kernel(const float* __restrict__ mass) {
    __shared__ float shP[64][KC + 1];
    __shared__ float shQ[64][KC + 1];

    int tile  = blockIdx.x;   // 0:(0,0) 1:(0,1) 2:(1,1)
    int chunk = blockIdx.y;   // 0..47
    int tp = (tile == 2) ? 1 : 0;
    int tq = (tile == 0) ? 0 : 1;
    int p0 = tp * 64, q0 = tq * 64;

    const float* src;
    int stride, d0;
    if (chunk < 8) { src = g_proj; stride = NI; d0 = chunk * 250; }
    else           { src = mass;   stride = NL; d0 = (chunk - 8) * 250; }

    int tx = threadIdx.x, ty = threadIdx.y;
    int tid = ty * 16 + tx;

    float acc[4][4] = {};

    for (int kb = 0; kb < 250; kb += KC) {
        for (int idx = tid; idx < 64 * KC; idx += 256) {
            int row = idx / KC, k = idx % KC;
            size_t off = (size_t)row * stride + d0 + kb + k;
            shP[row][k] = src[(size_t)p0 * stride + off];
            shQ[row][k] = src[(size_t)q0 * stride + off];
        }
        __syncthreads();

#pragma unroll 5
        for (int k = 0; k < KC; k++) {
            float a[4], b[4];
#pragma unroll
            for (int i = 0; i < 4; i++) a[i] = shP[ty + 16 * i][k];
#pragma unroll
            for (int j = 0; j < 4; j++) b[j] = shQ[tx + 16 * j][k];
#pragma unroll
            for (int i = 0; i < 4; i++)
#pragma unroll
                for (int j = 0; j < 4; j++)
                    acc[i][j] += fabsf(a[i] - b[j]);
        }
        __syncthreads();
    }

    float* part = g_partial + (size_t)chunk * ND * ND;
#pragma unroll
    for (int i = 0; i < 4; i++) {
        int p = p0 + ty + 16 * i;
#pragma unroll
        for (int j = 0; j < 4; j++) {
            int q = q0 + tx + 16 * j;
            part[p * ND + q] = acc[i][j];
        }
    }
}

// ---------------------------------------------------------------------------
// Kernel 4: reduce 48 partials, mirror lower triangle. Deterministic order.
// ---------------------------------------------------------------------------
__global__ __launch_bounds__(256) void reduce_kernel(float* __restrict__ out) {
    int idx = blockIdx.x * 256 + threadIdx.x;
    if (idx >= ND * ND) return;
    int p = idx / ND, q = idx % ND;
    int sp = p, sq = q;
    if ((p >> 6) > (q >> 6)) { sp = q; sq = p; }  // mirror lower tile
    float s = 0.f;
#pragma unroll
    for (int c = 0; c < NCHUNK; c++)
        s += g_partial[c * ND * ND + sp * ND + sq];
    out[idx] = s;
}

// ---------------------------------------------------------------------------
extern "C" void kernel_launch(void* const* d_in, const int* in_sizes, int n_in,
                              void* d_out, int out_size) {
    const float* mass  = (const float*)d_in[0];
    const float* param = (const float*)d_in[1];
    // robust to input ordering: param has 20M elements, mass 1.28M
    if (n_in >= 2 && in_sizes[0] == NI * NL) {
        param = (const float*)d_in[0];
        mass  = (const float*)d_in[1];
    }

    argmax_partial<<<dim3(40, RCHUNKS), 256>>>(param);
    argmax_reduce<<<40, 256>>>();
    proj_kernel<<<ND, 256>>>(mass);
    dist_kernel<<<dim3(3, NCHUNK), dim3(16, 16)>>>(mass);
    reduce_kernel<<<(ND * ND + 255) / 256, 256>>>((float*)d_out);
}